// round 10
// baseline (speedup 1.0000x reference)
#include <cuda_runtime.h>
#include <cstdint>

// Fused beam reorder + suffix append for KV cache.   [v8 256-bit ops, 128B/thread]
// Shapes: L=8, G=128, NH=8, T=128, HD=64, fp32.
//   out_k[l,g,h,t,:] = (t==pos) ? k_new[l,g,h,0,:] : k_buf[l,beam[g],h,t,:]
//   out_v analogous. Output = [k ; v] concatenated.
//
// float4 (16B) units: NEL4 = 2^24 per buffer; beam stride = 2^14.
//   t=(j>>4)&127; g=(j>>14)&127; gather src = j + (beam[g]-g)<<14
//   append src = ((j>>11)<<4)|(j&15)   ({k,v}_new is [L,G,NH,1,HD])
//
// Converged-model notes (R1-R9):
//  - Compulsory traffic ≈ 836 MB; measured ceiling 6.51-6.57 TB/s.
//  - Full-grid batch-phase launch REQUIRED: concurrent duplicate-beam readers
//    let L2 dedup reads (persistent pipeline broke this, +120 MB, R8).
//  - 256-bit v8 ld/st is the best-measured LSU shape (R9: 129.8 us kernel).
//  This round: 4 x v8 per thread (128 B), chunk 2048, grid 16384 — halves
//  per-block setup count, keeps front-batched loads + .cs streaming stores.
//  Each v8 covers float4 pair (j, j+1), j even: same t; gather delta and
//  append sidx are both even, so 32B alignment holds everywhere.

static constexpr unsigned NEL4   = 1u << 24;     // float4s per buffer
static constexpr unsigned TOTAL  = 1u << 25;     // k + v
static constexpr int      THREADS = 256;
static constexpr int      V8_PER_THREAD = 4;     // 4 x 32B = 128B/thread
static constexpr unsigned CHUNK  = THREADS * V8_PER_THREAD * 2;  // 2048 float4

__device__ __forceinline__ void ldg256(const float4* p, uint32_t r[8]) {
    asm volatile("ld.global.v8.b32 {%0,%1,%2,%3,%4,%5,%6,%7}, [%8];"
        : "=r"(r[0]), "=r"(r[1]), "=r"(r[2]), "=r"(r[3]),
          "=r"(r[4]), "=r"(r[5]), "=r"(r[6]), "=r"(r[7])
        : "l"(p));
}

__device__ __forceinline__ void stg256cs(float4* p, const uint32_t r[8]) {
    asm volatile("st.global.cs.v8.b32 [%0], {%1,%2,%3,%4,%5,%6,%7,%8};"
        :: "l"(p),
           "r"(r[0]), "r"(r[1]), "r"(r[2]), "r"(r[3]),
           "r"(r[4]), "r"(r[5]), "r"(r[6]), "r"(r[7])
        : "memory");
}

__global__ void __launch_bounds__(THREADS)
beam_reorder_append_kernel(const float4* __restrict__ kb,
                           const float4* __restrict__ vb,
                           const float4* __restrict__ kn,
                           const float4* __restrict__ vn,
                           const int*    __restrict__ beam,
                           const int*    __restrict__ posp,
                           float4*       __restrict__ out)
{
    const unsigned base = blockIdx.x * CHUNK;             // 2048-aligned
    const bool is_v = base >= NEL4;                       // uniform per block
    const unsigned jbase = base & (NEL4 - 1);

    const int pos = *posp;                                // L1-hit, uniform
    const unsigned g = (jbase >> 14) & 127;               // uniform per block
    const unsigned delta = ((unsigned)(beam[g] - (int)g)) << 14;  // uniform

    const float4* __restrict__ buf  = is_v ? vb : kb;
    const float4* __restrict__ nbuf = is_v ? vn : kn;

    uint32_t r[V8_PER_THREAD][8];

    // Front-batch all 4 independent 256-bit loads (128B/thread in flight).
    #pragma unroll
    for (int k = 0; k < V8_PER_THREAD; k++) {
        const unsigned j = jbase + 2u * (threadIdx.x + (unsigned)k * THREADS);
        const unsigned t = (j >> 4) & 127;                // same t for j, j+1
        const bool app = (t == (unsigned)pos);
        const unsigned sidx = app ? (((j >> 11) << 4) | (j & 15))
                                  : (j + delta);          // even -> 32B aligned
        const float4* __restrict__ src = app ? nbuf : buf;
        ldg256(src + sidx, r[k]);
    }

    // Streaming 256-bit stores: output never re-read.
    #pragma unroll
    for (int k = 0; k < V8_PER_THREAD; k++) {
        const unsigned o = base + 2u * (threadIdx.x + (unsigned)k * THREADS);
        stg256cs(out + o, r[k]);
    }
}

extern "C" void kernel_launch(void* const* d_in, const int* in_sizes, int n_in,
                              void* d_out, int out_size)
{
    const float4* kb   = (const float4*)d_in[0];  // k_buf  [L,G,NH,T,HD] fp32
    const float4* vb   = (const float4*)d_in[1];  // v_buf
    const float4* kn   = (const float4*)d_in[2];  // k_new  [L,G,NH,1,HD]
    const float4* vn   = (const float4*)d_in[3];  // v_new
    const int*    beam = (const int*)d_in[4];     // new_beam_idx [G]
    const int*    posp = (const int*)d_in[5];     // pos (scalar, device-side)
    float4*       out  = (float4*)d_out;          // [2,L,G,NH,T,HD] fp32

    const unsigned blocks = TOTAL / CHUNK;                // 16384
    beam_reorder_append_kernel<<<blocks, THREADS>>>(
        kb, vb, kn, vn, beam, posp, out);
}

// round 11
// speedup vs baseline: 1.0035x; 1.0035x over previous
#include <cuda_runtime.h>
#include <cstdint>

// Fused beam reorder + suffix append for KV cache.   [FINAL — R9 converged]
// Shapes: L=8, G=128, NH=8, T=128, HD=64, fp32.
//   out_k[l,g,h,t,:] = (t==pos) ? k_new[l,g,h,0,:] : k_buf[l,beam[g],h,t,:]
//   out_v analogous. Output = [k ; v] concatenated.
//
// float4 (16B) units: NEL4 = 2^24 per buffer; beam stride = 2^14.
//   t=(j>>4)&127; g=(j>>14)&127; gather src = j + (beam[g]-g)<<14
//   append src = ((j>>11)<<4)|(j&15)   ({k,v}_new is [L,G,NH,1,HD])
//
// Convergence evidence (R1-R10 sweep):
//  - Compulsory DRAM traffic ≈ 836 MB (512 MB writes + unique-beam reads;
//    E[unique]≈81/128; L2 dedups duplicates given full-grid concurrency).
//  - Measured ceiling 6.51-6.57 TB/s across ILP{1,4,8}, cache policies,
//    beam-sorted ordering, K+V fusion, persistent pipelining (which broke
//    dedup, +14% traffic), and v8 widths. Floor ≈ 128 us; this kernel: 129.8.
//  - Best shape: full-grid batch-phase, 64 B/thread as 2 front-batched
//    sm_100+ 256-bit loads (default policy), 2 x 256-bit .cs streaming
//    stores. Each v8 covers float4 pair (j, j+1), j even: same t, and both
//    gather delta and append sidx are even => 32B alignment everywhere.

static constexpr unsigned NEL4   = 1u << 24;     // float4s per buffer
static constexpr unsigned TOTAL  = 1u << 25;     // k + v
static constexpr int      THREADS = 256;
static constexpr unsigned CHUNK  = 1024;         // float4 per block (1024-aligned)
static constexpr int      V8_PER_THREAD = 2;     // 2 x 32B = 64B/thread

__device__ __forceinline__ void ldg256(const float4* p, uint32_t r[8]) {
    asm volatile("ld.global.v8.b32 {%0,%1,%2,%3,%4,%5,%6,%7}, [%8];"
        : "=r"(r[0]), "=r"(r[1]), "=r"(r[2]), "=r"(r[3]),
          "=r"(r[4]), "=r"(r[5]), "=r"(r[6]), "=r"(r[7])
        : "l"(p));
}

__device__ __forceinline__ void stg256cs(float4* p, const uint32_t r[8]) {
    asm volatile("st.global.cs.v8.b32 [%0], {%1,%2,%3,%4,%5,%6,%7,%8};"
        :: "l"(p),
           "r"(r[0]), "r"(r[1]), "r"(r[2]), "r"(r[3]),
           "r"(r[4]), "r"(r[5]), "r"(r[6]), "r"(r[7])
        : "memory");
}

__global__ void __launch_bounds__(THREADS, 8)
beam_reorder_append_kernel(const float4* __restrict__ kb,
                           const float4* __restrict__ vb,
                           const float4* __restrict__ kn,
                           const float4* __restrict__ vn,
                           const int*    __restrict__ beam,
                           const int*    __restrict__ posp,
                           float4*       __restrict__ out)
{
    const unsigned base = blockIdx.x * CHUNK;             // 1024-aligned
    const bool is_v = base >= NEL4;                       // uniform per block
    const unsigned jbase = base & (NEL4 - 1);

    const int pos = *posp;                                // L1-hit, uniform
    const unsigned g = (jbase >> 14) & 127;               // uniform per block
    const unsigned delta = ((unsigned)(beam[g] - (int)g)) << 14;  // uniform

    const float4* __restrict__ buf  = is_v ? vb : kb;
    const float4* __restrict__ nbuf = is_v ? vn : kn;

    uint32_t r[V8_PER_THREAD][8];

    // Front-batch both 256-bit loads (64B/thread in flight).
    #pragma unroll
    for (int k = 0; k < V8_PER_THREAD; k++) {
        // v8 unit index within chunk: threadIdx.x + k*256; float4 j = 2*that.
        const unsigned j = jbase + 2u * (threadIdx.x + (unsigned)k * THREADS);
        const unsigned t = (j >> 4) & 127;                // same t for j, j+1
        const bool app = (t == (unsigned)pos);
        const unsigned sidx = app ? (((j >> 11) << 4) | (j & 15))
                                  : (j + delta);          // even -> 32B aligned
        const float4* __restrict__ src = app ? nbuf : buf;
        ldg256(src + sidx, r[k]);
    }

    // Streaming 256-bit stores: output never re-read.
    #pragma unroll
    for (int k = 0; k < V8_PER_THREAD; k++) {
        const unsigned o = base + 2u * (threadIdx.x + (unsigned)k * THREADS);
        stg256cs(out + o, r[k]);
    }
}

extern "C" void kernel_launch(void* const* d_in, const int* in_sizes, int n_in,
                              void* d_out, int out_size)
{
    const float4* kb   = (const float4*)d_in[0];  // k_buf  [L,G,NH,T,HD] fp32
    const float4* vb   = (const float4*)d_in[1];  // v_buf
    const float4* kn   = (const float4*)d_in[2];  // k_new  [L,G,NH,1,HD]
    const float4* vn   = (const float4*)d_in[3];  // v_new
    const int*    beam = (const int*)d_in[4];     // new_beam_idx [G]
    const int*    posp = (const int*)d_in[5];     // pos (scalar, device-side)
    float4*       out  = (float4*)d_out;          // [2,L,G,NH,T,HD] fp32

    const unsigned blocks = TOTAL / CHUNK;                // 32768
    beam_reorder_append_kernel<<<blocks, THREADS>>>(
        kb, vb, kn, vn, beam, posp, out);
}

// round 12
// speedup vs baseline: 1.0102x; 1.0066x over previous
#include <cuda_runtime.h>
#include <cstdint>

// Fused beam reorder + suffix append for KV cache.  [R9 shape, 512-thr blocks]
// Shapes: L=8, G=128, NH=8, T=128, HD=64, fp32.
//   out_k[l,g,h,t,:] = (t==pos) ? k_new[l,g,h,0,:] : k_buf[l,beam[g],h,t,:]
//   out_v analogous. Output = [k ; v] concatenated.
//
// float4 (16B) units: NEL4 = 2^24 per buffer; beam stride = 2^14.
//   t=(j>>4)&127; g=(j>>14)&127; gather src = j + (beam[g]-g)<<14
//   append src = ((j>>11)<<4)|(j&15)   ({k,v}_new is [L,G,NH,1,HD])
//
// Convergence evidence (R1-R11):
//  - Compulsory traffic ≈ 836 MB; measured ceiling 6.51-6.57 TB/s across all
//    ILP/cache/order/fusion/pipeline/v8 variants (kernel 130.5 ± 0.5 us).
//  - Full-grid batch-phase launch required for L2 dedup of duplicate beams.
//  - Best per-thread shape: 2 front-batched sm_100+ 256-bit loads (default
//    policy) + 2 x 256-bit .cs streaming stores (64 B/thread).
//  This round: block size 256 -> 512 (only unswept dim). Chunk 2048 float4
//  still divides the 2^14 beam stride => g/is_v/delta block-uniform.

static constexpr unsigned NEL4   = 1u << 24;     // float4s per buffer
static constexpr unsigned TOTAL  = 1u << 25;     // k + v
static constexpr int      THREADS = 512;
static constexpr int      V8_PER_THREAD = 2;     // 2 x 32B = 64B/thread
static constexpr unsigned CHUNK  = THREADS * V8_PER_THREAD * 2;  // 2048 float4

__device__ __forceinline__ void ldg256(const float4* p, uint32_t r[8]) {
    asm volatile("ld.global.v8.b32 {%0,%1,%2,%3,%4,%5,%6,%7}, [%8];"
        : "=r"(r[0]), "=r"(r[1]), "=r"(r[2]), "=r"(r[3]),
          "=r"(r[4]), "=r"(r[5]), "=r"(r[6]), "=r"(r[7])
        : "l"(p));
}

__device__ __forceinline__ void stg256cs(float4* p, const uint32_t r[8]) {
    asm volatile("st.global.cs.v8.b32 [%0], {%1,%2,%3,%4,%5,%6,%7,%8};"
        :: "l"(p),
           "r"(r[0]), "r"(r[1]), "r"(r[2]), "r"(r[3]),
           "r"(r[4]), "r"(r[5]), "r"(r[6]), "r"(r[7])
        : "memory");
}

__global__ void __launch_bounds__(THREADS, 4)
beam_reorder_append_kernel(const float4* __restrict__ kb,
                           const float4* __restrict__ vb,
                           const float4* __restrict__ kn,
                           const float4* __restrict__ vn,
                           const int*    __restrict__ beam,
                           const int*    __restrict__ posp,
                           float4*       __restrict__ out)
{
    const unsigned base = blockIdx.x * CHUNK;             // 2048-aligned
    const bool is_v = base >= NEL4;                       // uniform per block
    const unsigned jbase = base & (NEL4 - 1);

    const int pos = *posp;                                // L1-hit, uniform
    const unsigned g = (jbase >> 14) & 127;               // uniform per block
    const unsigned delta = ((unsigned)(beam[g] - (int)g)) << 14;  // uniform

    const float4* __restrict__ buf  = is_v ? vb : kb;
    const float4* __restrict__ nbuf = is_v ? vn : kn;

    uint32_t r[V8_PER_THREAD][8];

    // Front-batch both 256-bit loads (64B/thread in flight).
    #pragma unroll
    for (int k = 0; k < V8_PER_THREAD; k++) {
        // v8 unit index within chunk: threadIdx.x + k*512; float4 j = 2*that.
        const unsigned j = jbase + 2u * (threadIdx.x + (unsigned)k * THREADS);
        const unsigned t = (j >> 4) & 127;                // same t for j, j+1
        const bool app = (t == (unsigned)pos);
        const unsigned sidx = app ? (((j >> 11) << 4) | (j & 15))
                                  : (j + delta);          // even -> 32B aligned
        const float4* __restrict__ src = app ? nbuf : buf;
        ldg256(src + sidx, r[k]);
    }

    // Streaming 256-bit stores: output never re-read.
    #pragma unroll
    for (int k = 0; k < V8_PER_THREAD; k++) {
        const unsigned o = base + 2u * (threadIdx.x + (unsigned)k * THREADS);
        stg256cs(out + o, r[k]);
    }
}

extern "C" void kernel_launch(void* const* d_in, const int* in_sizes, int n_in,
                              void* d_out, int out_size)
{
    const float4* kb   = (const float4*)d_in[0];  // k_buf  [L,G,NH,T,HD] fp32
    const float4* vb   = (const float4*)d_in[1];  // v_buf
    const float4* kn   = (const float4*)d_in[2];  // k_new  [L,G,NH,1,HD]
    const float4* vn   = (const float4*)d_in[3];  // v_new
    const int*    beam = (const int*)d_in[4];     // new_beam_idx [G]
    const int*    posp = (const int*)d_in[5];     // pos (scalar, device-side)
    float4*       out  = (float4*)d_out;          // [2,L,G,NH,T,HD] fp32

    const unsigned blocks = TOTAL / CHUNK;                // 16384
    beam_reorder_append_kernel<<<blocks, THREADS>>>(
        kb, vb, kn, vn, beam, posp, out);
}